// round 17
// baseline (speedup 1.0000x reference)
#include <cuda_runtime.h>
#include <cuda_fp16.h>
#include <cstdint>
#include <cstddef>

#define HW 4096
#define CIN 1088
#define CMID 136
#define CPAD 144

// ---------------- scratch (device globals; zero-initialized, no allocs) ----------------
__device__ float  g_feat[2][2][(size_t)CMID * HW];        // [a/b][n][c*HW+p]
__device__ float  g_E[2][(size_t)HW * HW];                // energy (already *100)
__device__ __half g_corr_h[2][2][(size_t)HW * HW];        // fp16 corr, [ab/ba][n], [k][l]
__device__ __half g_raw_h[2][2][(size_t)CIN * HW];        // [a/b][n]
__device__ __half g_fh[2][2][2][(size_t)CPAD * HW];       // [a/b][hi/lo][n], [c][p]
__device__ float  g_rowM[2][HW], g_rowSinv[2][HW];
__device__ float  g_colM[2][HW], g_colSinv[2][HW];
__device__ float  g_rowPm[2][32][HW],  g_rowPs[2][32][HW];
__device__ float  g_colPm[2][32][HW],  g_colPs[2][32][HW];

// ---------------- PTX helpers ----------------
__device__ __forceinline__ uint32_t smaddr(const void* p) {
    return (uint32_t)__cvta_generic_to_shared(p);
}
__device__ __forceinline__ void ldsm4(uint32_t r[4], const void* p) {
    asm volatile("ldmatrix.sync.aligned.m8n8.x4.shared.b16 {%0,%1,%2,%3}, [%4];\n"
                 : "=r"(r[0]), "=r"(r[1]), "=r"(r[2]), "=r"(r[3]) : "r"(smaddr(p)));
}
__device__ __forceinline__ void ldsm4t(uint32_t r[4], const void* p) {
    asm volatile("ldmatrix.sync.aligned.m8n8.x4.trans.shared.b16 {%0,%1,%2,%3}, [%4];\n"
                 : "=r"(r[0]), "=r"(r[1]), "=r"(r[2]), "=r"(r[3]) : "r"(smaddr(p)));
}
__device__ __forceinline__ void mma16816(float* d, const uint32_t* a, const uint32_t* b) {
    asm volatile("mma.sync.aligned.m16n8k16.row.col.f32.f16.f16.f32 "
                 "{%0,%1,%2,%3}, {%4,%5,%6,%7}, {%8,%9}, {%0,%1,%2,%3};\n"
                 : "+f"(d[0]), "+f"(d[1]), "+f"(d[2]), "+f"(d[3])
                 : "r"(a[0]), "r"(a[1]), "r"(a[2]), "r"(a[3]), "r"(b[0]), "r"(b[1]));
}
__device__ __forceinline__ void cpa16u(uint32_t sm, const void* g, int bytes) {
    asm volatile("cp.async.cg.shared.global [%0], [%1], 16, %2;\n"
                 :: "r"(sm), "l"(g), "r"(bytes));
}
#define CP_COMMIT() asm volatile("cp.async.commit_group;\n" ::: "memory")
#define CP_WAIT(n)  asm volatile("cp.async.wait_group %0;\n" :: "n"(n) : "memory")

// ---------------- K1: 1x1 conv via split-fp16 HMMA (per-n; z = tensor) ----------------
__global__ __launch_bounds__(256, 2) void conv_mma_kernel(
    int n,
    const float* __restrict__ fa, const float* __restrict__ fb,
    const float* __restrict__ Wa, const float* __restrict__ ba,
    const float* __restrict__ Wb, const float* __restrict__ bb) {
    extern __shared__ __align__(16) char csm[];
    float*  Xf  = (float*)csm;
    float*  Wf  = Xf + 32 * 256;
    __half* Xhl = (__half*)(Wf + 48 * 32);
    __half* Whl = Xhl + 2 * 32 * 264;

    const int t = blockIdx.z;
    const float* __restrict__ X = (t == 0 ? fa : fb) + (size_t)n * CIN * HW;
    const float* __restrict__ W = (t == 0 ? Wa : Wb);
    const float* __restrict__ bias = (t == 0 ? ba : bb);
    const int m0 = blockIdx.y * 48, n0 = blockIdx.x * 256;
    const int tid = threadIdx.x, lane = tid & 31, warp = tid >> 5;
    const int r16 = lane & 15, c8 = (lane >> 4) << 3;

    float acc[3][4][4];
#pragma unroll
    for (int i = 0; i < 3; ++i)
#pragma unroll
        for (int j = 0; j < 4; ++j)
#pragma unroll
            for (int k = 0; k < 4; ++k) acc[i][j][k] = 0.f;

    auto cpX = [&](int kc) {
#pragma unroll
        for (int i = 0; i < 8; ++i) {
            int idx = tid + i * 256;
            int row = idx >> 6, seg = (idx & 63) * 4;
            cpa16u(smaddr(&Xf[row * 256 + seg]), &X[(size_t)(kc + row) * HW + n0 + seg], 16);
        }
#pragma unroll
        for (int i = 0; i < 2; ++i) {
            int idx = tid + i * 256;
            if (idx < 384) {
                int row = idx >> 3, seg = (idx & 7) * 4;
                int o = m0 + row;
                int ok = o < CMID;
                cpa16u(smaddr(&Wf[row * 32 + seg]), &W[(size_t)(ok ? o : 0) * CIN + kc + seg], ok ? 16 : 0);
            }
        }
    };
    auto convert = [&]() {
        __half* Xh = Xhl;
        __half* Xl = Xh + 32 * 264;
#pragma unroll
        for (int i = 0; i < 32; ++i) {
            int idx = tid + i * 256;
            int row = idx >> 8, col = idx & 255;
            float v = Xf[row * 256 + col];
            __half h = __float2half_rn(v);
            Xh[row * 264 + col] = h;
            Xl[row * 264 + col] = __float2half_rn(v - __half2float(h));
        }
        __half* Wh = Whl;
        __half* Wl = Wh + 48 * 40;
#pragma unroll
        for (int i = 0; i < 6; ++i) {
            int idx = tid + i * 256;
            if (idx < 1536) {
                int row = idx >> 5, col = idx & 31;
                float v = Wf[row * 32 + col];
                __half h = __float2half_rn(v);
                Wh[row * 40 + col] = h;
                Wl[row * 40 + col] = __float2half_rn(v - __half2float(h));
            }
        }
    };

    cpX(0); CP_COMMIT();
    for (int j = 0; j < 34; ++j) {
        CP_WAIT(0);
        __syncthreads();      // orders: prev iter's mma reads done; this iter's cp.async data visible
        convert();
        __syncthreads();      // convert writes visible; Xf reads done before next load
        if (j + 1 < 34) cpX((j + 1) * 32);
        CP_COMMIT();

        const __half* Xh = Xhl;
        const __half* Xl = Xh + 32 * 264;
        const __half* Wh = Whl;
        const __half* Wl = Wh + 48 * 40;
#pragma unroll
        for (int ks = 0; ks < 32; ks += 16) {
            uint32_t ah[3][4], al[3][4], bh[2][4], bl[2][4];
#pragma unroll
            for (int mi = 0; mi < 3; ++mi) {
                ldsm4(ah[mi], &Wh[(mi * 16 + r16) * 40 + ks + c8]);
                ldsm4(al[mi], &Wl[(mi * 16 + r16) * 40 + ks + c8]);
            }
#pragma unroll
            for (int nj = 0; nj < 2; ++nj) {
                ldsm4t(bh[nj], &Xh[(ks + r16) * 264 + warp * 32 + nj * 16 + c8]);
                ldsm4t(bl[nj], &Xl[(ks + r16) * 264 + warp * 32 + nj * 16 + c8]);
            }
#pragma unroll
            for (int mi = 0; mi < 3; ++mi)
#pragma unroll
                for (int nj = 0; nj < 2; ++nj) {
                    mma16816(acc[mi][nj * 2],     ah[mi], &bh[nj][0]);
                    mma16816(acc[mi][nj * 2 + 1], ah[mi], &bh[nj][2]);
                    mma16816(acc[mi][nj * 2],     ah[mi], &bl[nj][0]);
                    mma16816(acc[mi][nj * 2 + 1], ah[mi], &bl[nj][2]);
                    mma16816(acc[mi][nj * 2],     al[mi], &bh[nj][0]);
                    mma16816(acc[mi][nj * 2 + 1], al[mi], &bh[nj][2]);
                }
        }
        // trailing barrier removed: next iteration's top barrier provides the ordering
    }

    float* __restrict__ Y = g_feat[t][n];
#pragma unroll
    for (int mi = 0; mi < 3; ++mi)
#pragma unroll
        for (int g = 0; g < 4; ++g) {
            int r0 = m0 + mi * 16 + (lane >> 2);
            int col = n0 + warp * 32 + (g >> 1) * 16 + (g & 1) * 8 + (lane & 3) * 2;
            if (r0 < CMID) {
                float bv = bias[r0];
                *(float2*)&Y[(size_t)r0 * HW + col] =
                    make_float2(acc[mi][g][0] + bv, acc[mi][g][1] + bv);
            }
            if (r0 + 8 < CMID) {
                float bv = bias[r0 + 8];
                *(float2*)&Y[(size_t)(r0 + 8) * HW + col] =
                    make_float2(acc[mi][g][2] + bv, acc[mi][g][3] + bv);
            }
        }
}

// ---------------- K2: InstanceNorm + LeakyReLU + mean-center (per-n; y = tensor) ----------------
__global__ void inorm_kernel(int n) {
    const int c = blockIdx.x, t = blockIdx.y;
    float* __restrict__ Y = &g_feat[t][n][(size_t)c * HW];
    __shared__ float sd[HW];
    __shared__ float r1[256], r2[256];
    const int tid = threadIdx.x;

    float s = 0.f, q = 0.f;
    for (int i = tid; i < HW; i += 256) { float v = Y[i]; sd[i] = v; s += v; q += v * v; }
    r1[tid] = s; r2[tid] = q; __syncthreads();
    for (int st = 128; st > 0; st >>= 1) {
        if (tid < st) { r1[tid] += r1[tid + st]; r2[tid] += r2[tid + st]; }
        __syncthreads();
    }
    const float mean = r1[0] * (1.f / HW);
    const float var  = r2[0] * (1.f / HW) - mean * mean;
    const float inv  = rsqrtf(var + 1e-5f);
    __syncthreads();

    float s2 = 0.f;
    for (int i = tid; i < HW; i += 256) {
        float v = (sd[i] - mean) * inv;
        v = (v >= 0.f) ? v : 0.2f * v;
        sd[i] = v; s2 += v;
    }
    r1[tid] = s2; __syncthreads();
    for (int st = 128; st > 0; st >>= 1) {
        if (tid < st) r1[tid] += r1[tid + st];
        __syncthreads();
    }
    const float mean2 = r1[0] * (1.f / HW);
    for (int i = tid; i < HW; i += 256) Y[i] = sd[i] - mean2;
}

// ---------------- K3: L2-normalize + split hi/lo (per-n; y = tensor) ----------------
__global__ void l2norm_kernel(int n) {
    const int tid = threadIdx.x;
    const int px = tid & 63, cg = tid >> 6;
    const int p = blockIdx.x * 64 + px;
    const int t = blockIdx.y;
    const float* __restrict__ F = g_feat[t][n];
    __shared__ float red[4][64];

    const int cbeg = cg * 34, cend = cbeg + 34;
    float q = 0.f;
    for (int c = cbeg; c < cend; ++c) { float v = F[(size_t)c * HW + p]; q += v * v; }
    red[cg][px] = q;
    __syncthreads();
    const float inv = rsqrtf(red[0][px] + red[1][px] + red[2][px] + red[3][px]);

    __half* __restrict__ hi = g_fh[t][0][n];
    __half* __restrict__ lo = g_fh[t][1][n];
    for (int c = cbeg; c < cend; ++c) {
        float v = F[(size_t)c * HW + p] * inv;
        __half h = __float2half_rn(v);
        hi[(size_t)c * HW + p] = h;
        lo[(size_t)c * HW + p] = __float2half_rn(v - __half2float(h));
    }
}

// ---------------- K4: energy, 128x128 tile, 256 thr, 2 CTAs/SM (per-n) ----------------
#define E2_T   (48 * 136)
#define E2_STG (4 * E2_T)
__global__ __launch_bounds__(256, 2) void energy_mma_kernel(int n) {
    extern __shared__ __align__(16) __half eshm[];

    const int m0 = blockIdx.y * 128, l0 = blockIdx.x * 128;
    const int tid = threadIdx.x, lane = tid & 31, warp = tid >> 5;
    const int wm = warp & 3, wn = warp >> 2;
    const int r16 = lane & 15, c8 = (lane >> 4) << 3;
    const int arow = (lane & 7) + ((lane >> 4) & 1) * 8;
    const int acol = ((lane >> 3) & 1) * 8;

    float acc[2][8][4];
#pragma unroll
    for (int i = 0; i < 2; ++i)
#pragma unroll
        for (int j = 0; j < 8; ++j)
#pragma unroll
            for (int k = 0; k < 4; ++k) acc[i][j][k] = 0.f;

    const uint32_t su = smaddr(eshm);
    auto loadst = [&](int st, int q) {
        const int kc = q * 48;
        const uint32_t SB = su + st * E2_STG * 2;
#pragma unroll
        for (int i = 0; i < 12; ++i) {
            int idx = tid + i * 256;
            int tile = idx / 768, ix = idx % 768;
            int row = ix >> 4, cp = (ix & 15) * 8;
            const __half* src = (tile < 2)
                ? &g_fh[1][tile][n][(size_t)(kc + row) * HW + m0 + cp]
                : &g_fh[0][tile - 2][n][(size_t)(kc + row) * HW + l0 + cp];
            cpa16u(SB + (tile * E2_T + row * 136 + cp) * 2, src, 16);
        }
    };

    auto mmag2 = [&](uint32_t a[2][4], uint32_t b[4][4]) {
#pragma unroll
        for (int mi = 0; mi < 2; ++mi)
#pragma unroll
            for (int nj = 0; nj < 4; ++nj) {
                mma16816(acc[mi][nj * 2],     a[mi], &b[nj][0]);
                mma16816(acc[mi][nj * 2 + 1], a[mi], &b[nj][2]);
            }
    };

    loadst(0, 0); CP_COMMIT();
    loadst(1, 1); CP_COMMIT();
#pragma unroll
    for (int q = 0; q < 3; ++q) {
        const int st = q & 1;
        if (q == 0) CP_WAIT(1); else CP_WAIT(0);
        __syncthreads();                 // top barrier: prev-iter reads done + data visible
        if (q == 1) { loadst(0, 2); CP_COMMIT(); }   // overwrite stage0 (reads completed per barrier)
        const __half* Ah = eshm + st * E2_STG;
        const __half* Al = Ah + E2_T;
        const __half* Bh = Al + E2_T;
        const __half* Bl = Bh + E2_T;
#pragma unroll
        for (int ks = 0; ks < 48; ks += 16) {
            uint32_t ah[2][4], bh[4][4];
#pragma unroll
            for (int mi = 0; mi < 2; ++mi)
                ldsm4t(ah[mi], Ah + (ks + arow) * 136 + wm * 32 + mi * 16 + acol);
#pragma unroll
            for (int nj = 0; nj < 4; ++nj)
                ldsm4t(bh[nj], Bh + (ks + r16) * 136 + wn * 64 + nj * 16 + c8);
            mmag2(ah, bh);
            {
                uint32_t bl[4][4];
#pragma unroll
                for (int nj = 0; nj < 4; ++nj)
                    ldsm4t(bl[nj], Bl + (ks + r16) * 136 + wn * 64 + nj * 16 + c8);
                mmag2(ah, bl);
            }
            {
                uint32_t al[2][4];
#pragma unroll
                for (int mi = 0; mi < 2; ++mi)
                    ldsm4t(al[mi], Al + (ks + arow) * 136 + wm * 32 + mi * 16 + acol);
                mmag2(al, bh);
            }
        }
        // trailing barrier removed
    }
    __syncthreads();   // before epilogue smem reuse

#pragma unroll
    for (int mi = 0; mi < 2; ++mi)
#pragma unroll
        for (int nj = 0; nj < 8; ++nj)
#pragma unroll
            for (int k = 0; k < 4; ++k) acc[mi][nj][k] *= 100.f;

    float* __restrict__ E = g_E[n];
#pragma unroll
    for (int mi = 0; mi < 2; ++mi)
#pragma unroll
        for (int nj = 0; nj < 8; ++nj) {
            int row = m0 + wm * 32 + mi * 16 + (lane >> 2);
            int col = l0 + wn * 64 + nj * 8 + (lane & 3) * 2;
            *(float2*)&E[(size_t)row * HW + col] = make_float2(acc[mi][nj][0], acc[mi][nj][1]);
            *(float2*)&E[(size_t)(row + 8) * HW + col] = make_float2(acc[mi][nj][2], acc[mi][nj][3]);
        }

    // ---- fused softmax partials ----
    float* sM   = (float*)eshm;
    float* sS   = sM + 256;
    float* cMax = sS + 256;
    float* cS   = cMax + 512;

#pragma unroll
    for (int mi = 0; mi < 2; ++mi)
#pragma unroll
        for (int h = 0; h < 2; ++h) {
            float m = -1e30f;
#pragma unroll
            for (int nj = 0; nj < 8; ++nj)
                m = fmaxf(m, fmaxf(acc[mi][nj][2 * h], acc[mi][nj][2 * h + 1]));
            m = fmaxf(m, __shfl_xor_sync(0xFFFFFFFFu, m, 1));
            m = fmaxf(m, __shfl_xor_sync(0xFFFFFFFFu, m, 2));
            float s = 0.f;
#pragma unroll
            for (int nj = 0; nj < 8; ++nj)
                s += __expf(acc[mi][nj][2 * h] - m) + __expf(acc[mi][nj][2 * h + 1] - m);
            s += __shfl_xor_sync(0xFFFFFFFFu, s, 1);
            s += __shfl_xor_sync(0xFFFFFFFFu, s, 2);
            if ((lane & 3) == 0) {
                int r = wm * 32 + mi * 16 + (lane >> 2) + 8 * h;
                sM[wn * 128 + r] = m;
                sS[wn * 128 + r] = s;
            }
        }
    float m16[8][2];
#pragma unroll
    for (int nj = 0; nj < 8; ++nj)
#pragma unroll
        for (int c = 0; c < 2; ++c) {
            float m = fmaxf(fmaxf(acc[0][nj][c], acc[0][nj][2 + c]),
                            fmaxf(acc[1][nj][c], acc[1][nj][2 + c]));
            m = fmaxf(m, __shfl_xor_sync(0xFFFFFFFFu, m, 4));
            m = fmaxf(m, __shfl_xor_sync(0xFFFFFFFFu, m, 8));
            m = fmaxf(m, __shfl_xor_sync(0xFFFFFFFFu, m, 16));
            m16[nj][c] = m;
        }
    if ((lane >> 2) == 0) {
#pragma unroll
        for (int nj = 0; nj < 8; ++nj)
#pragma unroll
            for (int c = 0; c < 2; ++c)
                cMax[wm * 128 + wn * 64 + nj * 8 + (lane & 3) * 2 + c] = m16[nj][c];
    }
    __syncthreads();

    if (tid < 128) {
        float M = sM[tid], S = sS[tid];
        float m2 = sM[128 + tid], s2 = sS[128 + tid];
        float M2 = fmaxf(M, m2);
        S = S * __expf(M - M2) + s2 * __expf(m2 - M2);
        M = M2;
        g_rowPm[n][blockIdx.x][m0 + tid] = M;
        g_rowPs[n][blockIdx.x][m0 + tid] = S;
        float C = fmaxf(fmaxf(cMax[tid], cMax[128 + tid]),
                        fmaxf(cMax[256 + tid], cMax[384 + tid]));
        cMax[tid] = C;
    }
    __syncthreads();

    float s16[8][2];
#pragma unroll
    for (int nj = 0; nj < 8; ++nj)
#pragma unroll
        for (int c = 0; c < 2; ++c) {
            float bm = cMax[wn * 64 + nj * 8 + (lane & 3) * 2 + c];
            float s = __expf(acc[0][nj][c] - bm) + __expf(acc[0][nj][2 + c] - bm)
                    + __expf(acc[1][nj][c] - bm) + __expf(acc[1][nj][2 + c] - bm);
            s += __shfl_xor_sync(0xFFFFFFFFu, s, 4);
            s += __shfl_xor_sync(0xFFFFFFFFu, s, 8);
            s += __shfl_xor_sync(0xFFFFFFFFu, s, 16);
            s16[nj][c] = s;
        }
    if ((lane >> 2) == 0) {
#pragma unroll
        for (int nj = 0; nj < 8; ++nj)
#pragma unroll
            for (int c = 0; c < 2; ++c)
                cS[wm * 128 + wn * 64 + nj * 8 + (lane & 3) * 2 + c] = s16[nj][c];
    }
    __syncthreads();
    if (tid < 128) {
        float S = cS[tid] + cS[128 + tid] + cS[256 + tid] + cS[384 + tid];
        g_colPm[n][blockIdx.y][l0 + tid] = cMax[tid];
        g_colPs[n][blockIdx.y][l0 + tid] = S;
    }
}

// ---------------- K5: combine partial stats (per-n; y: 0=row 1=col) ----------------
__global__ void combine_kernel(int n) {
    const int i = blockIdx.x * 256 + threadIdx.x;
    float M = -1e30f, S = 0.f;
    if (blockIdx.y == 0) {
#pragma unroll
        for (int b = 0; b < 32; ++b) {
            float m = g_rowPm[n][b][i], s = g_rowPs[n][b][i];
            float M2 = fmaxf(M, m);
            S = S * __expf(M - M2) + s * __expf(m - M2);
            M = M2;
        }
        g_rowM[n][i] = M;
        g_rowSinv[n][i] = 1.0f / S;
    } else {
#pragma unroll
        for (int b = 0; b < 32; ++b) {
            float m = g_colPm[n][b][i], s = g_colPs[n][b][i];
            float M2 = fmaxf(M, m);
            S = S * __expf(M - M2) + s * __expf(m - M2);
            M = M2;
        }
        g_colM[n][i] = M;
        g_colSinv[n][i] = 1.0f / S;
    }
}

// ---------------- K6: softmax writeout, vectorized (per-n) ----------------
__global__ void writeout_kernel(int n, float* __restrict__ out_ab, float* __restrict__ out_ba) {
    const int c0 = blockIdx.x * 64, r0 = blockIdx.y * 64;
    const int tid = threadIdx.x;
    const int tx = tid & 15, ty = tid >> 4;
    const float* __restrict__ E = g_E[n];
    __half* __restrict__ Hab = g_corr_h[0][n];
    __half* __restrict__ Hba = g_corr_h[1][n];
    float* __restrict__ Oab = out_ab + (size_t)n * HW * HW;
    float* __restrict__ Oba = out_ba + (size_t)n * HW * HW;

    __shared__ float t_ba[64][68];
    __shared__ float rm_s[64], rsi_s[64];
    if (tid < 64)       rm_s[tid]       = g_rowM[n][r0 + tid];
    else if (tid < 128) rsi_s[tid - 64] = g_rowSinv[n][r0 + tid - 64];
    const float4 cm4  = *(const float4*)&g_colM[n][c0 + tx * 4];
    const float4 csi4 = *(const float4*)&g_colSinv[n][c0 + tx * 4];
    __syncthreads();

#pragma unroll
    for (int it = 0; it < 4; ++it) {
        int r_in = it * 16 + ty;
        int R = r0 + r_in;
        float4 e = *(const float4*)&E[(size_t)R * HW + c0 + tx * 4];
        float rm = rm_s[r_in], rsi = rsi_s[r_in];
        float4 pr = make_float4(__expf(e.x - rm) * rsi, __expf(e.y - rm) * rsi,
                                __expf(e.z - rm) * rsi, __expf(e.w - rm) * rsi);
        float pc0 = __expf(e.x - cm4.x) * csi4.x;
        float pc1 = __expf(e.y - cm4.y) * csi4.y;
        float pc2 = __expf(e.z - cm4.z) * csi4.z;
        float pc3 = __expf(e.w - cm4.w) * csi4.w;
        size_t off = (size_t)R * HW + c0 + tx * 4;
        *(float4*)&Oab[off] = pr;
        __half2 h0 = __floats2half2_rn(pr.x, pr.y);
        __half2 h1 = __floats2half2_rn(pr.z, pr.w);
        *(uint2*)&Hab[off] = make_uint2(*(uint32_t*)&h0, *(uint32_t*)&h1);
        t_ba[tx * 4 + 0][r_in] = pc0;
        t_ba[tx * 4 + 1][r_in] = pc1;
        t_ba[tx * 4 + 2][r_in] = pc2;
        t_ba[tx * 4 + 3][r_in] = pc3;
    }
    __syncthreads();
#pragma unroll
    for (int it = 0; it < 4; ++it) {
        int c_in = it * 16 + ty;
        float4 p = *(const float4*)&t_ba[c_in][tx * 4];
        size_t off = (size_t)(c0 + c_in) * HW + r0 + tx * 4;
        *(float4*)&Oba[off] = p;
        __half2 h0 = __floats2half2_rn(p.x, p.y);
        __half2 h1 = __floats2half2_rn(p.z, p.w);
        *(uint2*)&Hba[off] = make_uint2(*(uint32_t*)&h0, *(uint32_t*)&h1);
    }
}

// ---------------- K7: raw -> fp16 ----------------
__global__ void tohalf_kernel(const float* __restrict__ a_raw, const float* __restrict__ b_raw) {
    const int t = blockIdx.y;
    const float* __restrict__ src = (t == 0 ? a_raw : b_raw);
    __half* __restrict__ dst = &g_raw_h[t][0][0];
    size_t i = ((size_t)blockIdx.x * 256 + threadIdx.x) * 4;
    float4 v = *(const float4*)&src[i];
    __half2* d2 = (__half2*)&dst[i];
    d2[0] = __floats2half2_rn(v.x, v.y);
    d2[1] = __floats2half2_rn(v.z, v.w);
}

// ---------------- K8: warp matmul, 128x128 tile, 256 thr, 2 CTAs/SM, 3-stage (per-n) ----------------
#define G2_AST (128 * 72)
#define G2_BST (64 * 136)
#define G2_NC 64
__global__ __launch_bounds__(256, 2) void wgemm_kernel(int n, float* __restrict__ out) {
    extern __shared__ __align__(16) __half gshm[];
    __half* As = gshm;
    __half* Bs = gshm + 3 * G2_AST;
    const uint32_t su = smaddr(gshm);

    const int dir = blockIdx.z;
    const __half* __restrict__ A = g_raw_h[dir][n];
    const __half* __restrict__ B = g_corr_h[dir ^ 1][n];
    float* __restrict__ C = out + (size_t)4 * HW * HW
                                + (size_t)dir * 2 * CIN * HW + (size_t)n * CIN * HW;
    const int m0 = blockIdx.y * 128, n0 = blockIdx.x * 128;
    const int tid = threadIdx.x, lane = tid & 31, warp = tid >> 5;
    const int wm = warp & 3, wn = warp >> 2;
    const int r16 = lane & 15, c8 = (lane >> 4) << 3;

    float acc[2][8][4];
#pragma unroll
    for (int i = 0; i < 2; ++i)
#pragma unroll
        for (int j = 0; j < 8; ++j)
#pragma unroll
            for (int k = 0; k < 4; ++k) acc[i][j][k] = 0.f;

    auto loadst = [&](int st, int j) {
        const int k0 = j * 64;
#pragma unroll
        for (int i = 0; i < 8; ++i) {
            int idx = tid + i * 256;
            if (idx < 1024) {
                int row = idx >> 3, cp = (idx & 7) * 8;
                int gr = m0 + row;
                int ok = gr < CIN;
                cpa16u(su + (st * G2_AST + row * 72 + cp) * 2,
                       &A[(size_t)(ok ? gr : 0) * HW + k0 + cp], ok ? 16 : 0);
            } else {
                int ix = idx - 1024;
                int row = ix >> 4, cp = (ix & 15) * 8;
                cpa16u(su + (3 * G2_AST + st * G2_BST + row * 136 + cp) * 2,
                       &B[(size_t)(k0 + row) * HW + n0 + cp], 16);
            }
        }
    };

    loadst(0, 0); CP_COMMIT();
    loadst(1, 1); CP_COMMIT();

    for (int j = 0; j < G2_NC; ++j) {
        const int st = j % 3;
        if (j + 1 < G2_NC) CP_WAIT(1); else CP_WAIT(0);
        __syncthreads();      // top barrier: prev-iter ldsm reads done + stage-j data visible
        if (j + 2 < G2_NC) { loadst((j + 2) % 3, j + 2); CP_COMMIT(); }

#pragma unroll
        for (int ks = 0; ks < 64; ks += 16) {
            uint32_t a[2][4], b[4][4];
#pragma unroll
            for (int mi = 0; mi < 2; ++mi)
                ldsm4(a[mi], As + st * G2_AST + (wm * 32 + mi * 16 + r16) * 72 + ks + c8);
#pragma unroll
            for (int nj = 0; nj < 4; ++nj)
                ldsm4t(b[nj], Bs + st * G2_BST + (ks + r16) * 136 + wn * 64 + nj * 16 + c8);
#pragma unroll
            for (int mi = 0; mi < 2; ++mi)
#pragma unroll
                for (int nj = 0; nj < 4; ++nj) {
                    mma16816(acc[mi][nj * 2],     a[mi], &b[nj][0]);
                    mma16816(acc[mi][nj * 2 + 1], a[mi], &b[nj][2]);
                }
        }
        // trailing barrier removed: stage (j+2)%3 overwrite is ordered by next iter's top barrier
    }

#pragma unroll
    for (int mi = 0; mi < 2; ++mi)
#pragma unroll
        for (int nj = 0; nj < 8; ++nj) {
            int row = m0 + wm * 32 + mi * 16 + (lane >> 2);
            int col = n0 + wn * 64 + nj * 8 + (lane & 3) * 2;
            if (row < CIN)
                *(float2*)&C[(size_t)row * HW + col] = make_float2(acc[mi][nj][0], acc[mi][nj][1]);
            if (row + 8 < CIN)
                *(float2*)&C[(size_t)(row + 8) * HW + col] = make_float2(acc[mi][nj][2], acc[mi][nj][3]);
        }
}

// ---------------- launch ----------------
extern "C" void kernel_launch(void* const* d_in, const int* in_sizes, int n_in,
                              void* d_out, int out_size) {
    const float* fa    = (const float*)d_in[0];
    const float* fb    = (const float*)d_in[1];
    const float* a_raw = (const float*)d_in[2];
    const float* b_raw = (const float*)d_in[3];
    const float* Wa    = (const float*)d_in[4];
    const float* ba    = (const float*)d_in[5];
    const float* Wb    = (const float*)d_in[6];
    const float* bb    = (const float*)d_in[7];
    float* out = (float*)d_out;
    float* out_ab = out;
    float* out_ba = out + (size_t)2 * HW * HW;

    const int c_smem = 32 * 256 * 4 + 48 * 32 * 4 + 2 * 32 * 264 * 2 + 2 * 48 * 40 * 2; // 80384
    const int e_smem = 2 * E2_STG * 2;                   // 104448
    const int g_smem = 3 * (G2_AST + G2_BST) * 2;        // 107520
    cudaFuncSetAttribute(conv_mma_kernel, cudaFuncAttributeMaxDynamicSharedMemorySize, c_smem);
    cudaFuncSetAttribute(energy_mma_kernel, cudaFuncAttributeMaxDynamicSharedMemorySize, e_smem);
    cudaFuncSetAttribute(wgemm_kernel, cudaFuncAttributeMaxDynamicSharedMemorySize, g_smem);

    // ONE extra stream (proven capture-safe); full n=1 chain rides it.
    cudaStream_t s2;
    cudaStreamCreate(&s2);
    cudaEvent_t ef, eT, eB;
    cudaEventCreateWithFlags(&ef, cudaEventDisableTiming);
    cudaEventCreateWithFlags(&eT, cudaEventDisableTiming);
    cudaEventCreateWithFlags(&eB, cudaEventDisableTiming);

    // fork s2 from the capture stream
    cudaEventRecord(ef, 0);
    cudaStreamWaitEvent(s2, ef, 0);

    // stream 0: tohalf first (feeds both wgemms), then the full n=0 chain
    tohalf_kernel<<<dim3(8704, 2), 256>>>(a_raw, b_raw);
    cudaEventRecord(eT, 0);
    conv_mma_kernel<<<dim3(16, 3, 2), 256, c_smem>>>(0, fa, fb, Wa, ba, Wb, bb);
    inorm_kernel<<<dim3(CMID, 2), 256>>>(0);
    l2norm_kernel<<<dim3(HW / 64, 2), 256>>>(0);
    energy_mma_kernel<<<dim3(32, 32), 256, e_smem>>>(0);
    combine_kernel<<<dim3(HW / 256, 2), 256>>>(0);
    writeout_kernel<<<dim3(64, 64), 256>>>(0, out_ab, out_ba);
    wgemm_kernel<<<dim3(32, 9, 2), 256, g_smem>>>(0, out);

    // s2: full n=1 chain (waits on eT only before its wgemm)
    conv_mma_kernel<<<dim3(16, 3, 2), 256, c_smem, s2>>>(1, fa, fb, Wa, ba, Wb, bb);
    inorm_kernel<<<dim3(CMID, 2), 256, 0, s2>>>(1);
    l2norm_kernel<<<dim3(HW / 64, 2), 256, 0, s2>>>(1);
    energy_mma_kernel<<<dim3(32, 32), 256, e_smem, s2>>>(1);
    combine_kernel<<<dim3(HW / 256, 2), 256, 0, s2>>>(1);
    writeout_kernel<<<dim3(64, 64), 256, 0, s2>>>(1, out_ab, out_ba);
    cudaStreamWaitEvent(s2, eT, 0);
    wgemm_kernel<<<dim3(32, 9, 2), 256, g_smem, s2>>>(1, out);
    cudaEventRecord(eB, s2);

    // join
    cudaStreamWaitEvent(0, eB, 0);
}